// round 4
// baseline (speedup 1.0000x reference)
#include <cuda_runtime.h>
#include <cuda_bf16.h>
#include <cstdint>

// Problem constants
#define BB 1024
#define RR 8
#define CC 1024
#define DD 16384
#define KK 32
#define NCAND 64
#define SST 40     // smem row stride in bf16 (80B: 16B aligned, LDSM conflict-free)

// ---------------- device scratch (allocation-free rule: __device__ globals) ----
__device__ __nv_bfloat16 g_h  [(size_t)BB * RR * DD];        // 256 MB approx h (bf16)
__device__ float         g_xc [(size_t)BB * RR * CC];        // 32 MB  x - decoder_b (fp32)
__device__ __nv_bfloat16 g_Ah [(size_t)RR * BB * CC];        // 16 MB  bf16 activations [r][b][c]
__device__ __nv_bfloat16 g_Bh [(size_t)RR * DD * CC];        // 256 MB bf16 enc weights [r][d][c]
__device__ float         g_dwT[(size_t)RR * DD * CC];        // 512 MB decoder_w transposed
__device__ int           g_cand[(size_t)BB * RR * NCAND];    // 2 MB   top-64 candidates
__device__ float         g_vals[(size_t)BB * RR * KK];
__device__ int           g_idx [(size_t)BB * RR * KK];

// ---------------- prep: xc = x - decoder_b (fp32) + bf16 copy -----------------
__global__ void prep_x_kernel(const float* __restrict__ x,
                              const float* __restrict__ db) {
    int idx = blockIdx.x * blockDim.x + threadIdx.x;   // over B*R*C
    int b = idx >> 13;
    int r = (idx >> 10) & 7;
    int c = idx & 1023;
    float xc = x[idx] - db[r * CC + c];
    g_xc[idx] = xc;
    g_Ah[((size_t)r * BB + b) * CC + c] = __float2bfloat16(xc);
}

__global__ void prep_w_kernel(const float* __restrict__ ew) {
    int idx = blockIdx.x * blockDim.x + threadIdx.x;   // over R*D*C
    g_Bh[idx] = __float2bfloat16(ew[idx]);
}

// ---------------- decoder_w transpose: [r][c][d] -> [r][d][c] -----------------
__global__ void transpose_dw_kernel(const float* __restrict__ dw) {
    __shared__ float tile[32][33];
    int d0 = blockIdx.x * 32;
    int c0 = blockIdx.y * 32;
    int r  = blockIdx.z;
    int tx = threadIdx.x, ty = threadIdx.y;   // (32, 8)
    #pragma unroll
    for (int j = 0; j < 4; j++) {
        int c = c0 + ty + j * 8;
        tile[ty + j * 8][tx] = dw[((size_t)r * CC + c) * DD + d0 + tx];
    }
    __syncthreads();
    #pragma unroll
    for (int j = 0; j < 4; j++) {
        int d = d0 + ty + j * 8;
        g_dwT[((size_t)r * DD + d) * CC + c0 + tx] = tile[tx][ty + j * 8];
    }
}

// ---------------- approx encoder GEMM: bf16 mma m16n8k16, K=1024 --------------
// Block 128x128, 4 warps (2x2), warp tile 64x64. cp.async 2-stage + ldmatrix.

__device__ __forceinline__ void mma16816(float* c, const uint32_t* a,
                                         uint32_t b0, uint32_t b1) {
    asm volatile(
        "mma.sync.aligned.m16n8k16.row.col.f32.bf16.bf16.f32 "
        "{%0,%1,%2,%3}, {%4,%5,%6,%7}, {%8,%9}, {%0,%1,%2,%3};\n"
        : "+f"(c[0]), "+f"(c[1]), "+f"(c[2]), "+f"(c[3])
        : "r"(a[0]), "r"(a[1]), "r"(a[2]), "r"(a[3]), "r"(b0), "r"(b1));
}

__device__ __forceinline__ void ldsm4(uint32_t* d, uint32_t addr) {
    asm volatile("ldmatrix.sync.aligned.m8n8.x4.shared.b16 {%0,%1,%2,%3}, [%4];"
                 : "=r"(d[0]), "=r"(d[1]), "=r"(d[2]), "=r"(d[3]) : "r"(addr));
}

__global__ __launch_bounds__(128, 2)
void encoder_gemm_kernel(const __nv_bfloat16* __restrict__ Ap,
                         const __nv_bfloat16* __restrict__ Bp,
                         const float* __restrict__ eb,
                         __nv_bfloat16* __restrict__ H) {
    const int mt = blockIdx.x;        // 8 M-tiles (fastest: B'-tile L2 reuse)
    const int nt = blockIdx.y;        // 128 N-tiles
    const int r  = blockIdx.z;        // 8
    const int tid = threadIdx.x;
    const int wid = tid >> 5, lane = tid & 31;
    const int wm = wid >> 1, wn = wid & 1;        // 2x2 warps, 64x64 per warp
    const int g = lane >> 2, t = lane & 3;

    __shared__ __nv_bfloat16 sA[2][128 * SST];
    __shared__ __nv_bfloat16 sB[2][128 * SST];

    float acc[4][8][4];
    #pragma unroll
    for (int i = 0; i < 4; i++)
        #pragma unroll
        for (int j = 0; j < 8; j++)
            #pragma unroll
            for (int q = 0; q < 4; q++) acc[i][j][q] = 0.f;

    // global->smem: 512 16B-segments per operand per kt; 128 threads x 4 each
    const int row = tid >> 2, col = (tid & 3) * 8;     // +j*32 rows
    size_t aG[4], bG[4];
    #pragma unroll
    for (int j = 0; j < 4; j++) {
        aG[j] = ((size_t)r * BB + mt * 128 + row + j * 32) * CC + col;
        bG[j] = ((size_t)r * DD + nt * 128 + row + j * 32) * CC + col;
    }
    const uint32_t sA0 = (uint32_t)__cvta_generic_to_shared(&sA[0][0]);
    const uint32_t sB0 = (uint32_t)__cvta_generic_to_shared(&sB[0][0]);
    const uint32_t bufBytes = 128 * SST * 2;
    const uint32_t sDst = (row * SST + col) * 2;

    auto prefetch = [&](int kt, int buf) {
        #pragma unroll
        for (int j = 0; j < 4; j++) {
            uint32_t da = sA0 + buf * bufBytes + sDst + j * 32 * SST * 2;
            uint32_t db = sB0 + buf * bufBytes + sDst + j * 32 * SST * 2;
            asm volatile("cp.async.cg.shared.global [%0], [%1], 16;\n"
                         :: "r"(da), "l"(Ap + aG[j] + kt * 32) : "memory");
            asm volatile("cp.async.cg.shared.global [%0], [%1], 16;\n"
                         :: "r"(db), "l"(Bp + bG[j] + kt * 32) : "memory");
        }
        asm volatile("cp.async.commit_group;\n" ::: "memory");
    };

    // ldmatrix per-lane offsets (bytes within buffer)
    const uint32_t fRow = lane & 15;
    const uint32_t fK   = (lane >> 4) * 8;
    const uint32_t aF = ((wm * 64 + fRow) * SST + fK) * 2;
    const uint32_t bF = ((wn * 64 + fRow) * SST + fK) * 2;

    prefetch(0, 0);
    const int NKT = CC / 32;   // 32
    for (int kt = 0; kt < NKT; kt++) {
        asm volatile("cp.async.wait_group 0;\n" ::: "memory");
        __syncthreads();                                  // data ready + prev compute done
        if (kt + 1 < NKT) prefetch(kt + 1, (kt + 1) & 1);
        const int buf = kt & 1;
        const uint32_t baseA = sA0 + buf * bufBytes + aF;
        const uint32_t baseB = sB0 + buf * bufBytes + bF;
        #pragma unroll
        for (int ks = 0; ks < 2; ks++) {
            const int ko = ks * 16;
            uint32_t afr[4][4], bq[4][4];
            #pragma unroll
            for (int mi = 0; mi < 4; mi++) ldsm4(afr[mi], baseA + (mi * 16 * SST + ko) * 2);
            #pragma unroll
            for (int nb = 0; nb < 4; nb++) ldsm4(bq[nb], baseB + (nb * 16 * SST + ko) * 2);
            #pragma unroll
            for (int mi = 0; mi < 4; mi++)
                #pragma unroll
                for (int nb = 0; nb < 4; nb++) {
                    mma16816(acc[mi][2 * nb],     afr[mi], bq[nb][0], bq[nb][2]);
                    mma16816(acc[mi][2 * nb + 1], afr[mi], bq[nb][1], bq[nb][3]);
                }
        }
    }

    // epilogue: h = acc + encoder_b -> bf16
    const size_t ebBase = (size_t)r * DD;
    #pragma unroll
    for (int mi = 0; mi < 4; mi++) {
        int b0 = mt * 128 + wm * 64 + mi * 16 + g;
        #pragma unroll
        for (int ni = 0; ni < 8; ni++) {
            int d0 = nt * 128 + wn * 64 + ni * 8 + 2 * t;
            float e0 = eb[ebBase + d0];
            float e1 = eb[ebBase + d0 + 1];
            __nv_bfloat162 v0, v1;
            v0.x = __float2bfloat16(acc[mi][ni][0] + e0);
            v0.y = __float2bfloat16(acc[mi][ni][1] + e1);
            v1.x = __float2bfloat16(acc[mi][ni][2] + e0);
            v1.y = __float2bfloat16(acc[mi][ni][3] + e1);
            *(__nv_bfloat162*)&H[((size_t)b0 * RR + r) * DD + d0]       = v0;
            *(__nv_bfloat162*)&H[((size_t)(b0 + 8) * RR + r) * DD + d0] = v1;
        }
    }
}

// ---------------- approx top-64 candidates: 2-pass radix on 16-bit bf16 keys --
__global__ __launch_bounds__(256)
void topk_kernel(const __nv_bfloat16* __restrict__ H) {
    __shared__ uint16_t skey[DD];             // 32 KB
    __shared__ int hist[256];
    __shared__ int s_sel, s_remaining, s_cnt, s_tiecnt;
    __shared__ int out_idx[NCAND];
    __shared__ int tie_idx[192];

    const int row = blockIdx.x;               // b*R + r
    const int tid = threadIdx.x;              // 256 threads
    const uint4* h4 = (const uint4*)(H + (size_t)row * DD);

    for (int c = tid; c < DD / 8; c += 256) {
        uint4 v = h4[c];
        uint32_t ws[4] = {v.x, v.y, v.z, v.w};
        #pragma unroll
        for (int q = 0; q < 4; q++) {
            uint16_t lo = (uint16_t)(ws[q] & 0xFFFF);
            uint16_t hi = (uint16_t)(ws[q] >> 16);
            skey[c * 8 + 2 * q]     = (lo & 0x8000) ? (uint16_t)~lo : (uint16_t)(lo | 0x8000);
            skey[c * 8 + 2 * q + 1] = (hi & 0x8000) ? (uint16_t)~hi : (uint16_t)(hi | 0x8000);
        }
    }
    hist[tid] = 0;
    __syncthreads();

    // pass 1: high byte
    for (int i = tid; i < DD; i += 256) atomicAdd(&hist[skey[i] >> 8], 1);
    __syncthreads();
    if (tid == 0) {
        int cum = 0, v = 255;
        for (; v > 0; v--) {
            if (cum + hist[v] >= NCAND) break;
            cum += hist[v];
        }
        s_sel = v;
        s_remaining = NCAND - cum;
    }
    __syncthreads();
    const int hb = s_sel;
    const int rem = s_remaining;
    __syncthreads();
    hist[tid] = 0;
    __syncthreads();

    // pass 2: low byte within selected high byte
    for (int i = tid; i < DD; i += 256) {
        uint16_t k = skey[i];
        if ((k >> 8) == hb) atomicAdd(&hist[k & 0xFF], 1);
    }
    __syncthreads();
    if (tid == 0) {
        int cum = 0, v = 255;
        for (; v > 0; v--) {
            if (cum + hist[v] >= rem) break;
            cum += hist[v];
        }
        s_sel = (hb << 8) | v;
        s_cnt = 0;
        s_tiecnt = 0;
    }
    __syncthreads();
    const uint16_t T = (uint16_t)s_sel;

    // collect candidates
    for (int i = tid; i < DD; i += 256) {
        uint16_t k = skey[i];
        if (k > T) {
            int p = atomicAdd(&s_cnt, 1);
            out_idx[p] = i;                   // strictly-greater count < NCAND by construction
        } else if (k == T) {
            int p = atomicAdd(&s_tiecnt, 1);
            if (p < 192) tie_idx[p] = i;
        }
    }
    __syncthreads();
    if (tid == 0) {
        int gcnt = s_cnt;
        int need = NCAND - gcnt;              // >= 1
        if (s_tiecnt <= 192) {
            for (int a = 0; a < need; a++) out_idx[gcnt + a] = tie_idx[a];
        } else {
            int taken = 0;
            for (int i = 0; i < DD && taken < need; i++)
                if (skey[i] == T) out_idx[gcnt + taken++] = i;
        }
    }
    __syncthreads();
    if (tid < NCAND) g_cand[(size_t)row * NCAND + tid] = out_idx[tid];
}

// ---------------- exact fp32 refine of 64 candidates -> top-32 ----------------
__global__ __launch_bounds__(256)
void refine_kernel(const float* __restrict__ ew, const float* __restrict__ eb) {
    __shared__ float sxc[CC];                 // 4 KB xc row
    __shared__ float sval[NCAND];
    __shared__ int   scand[NCAND];

    const int row = blockIdx.x;               // b*R + r
    const int r   = row & 7;
    const int tid = threadIdx.x;
    const int wid = tid >> 5, lane = tid & 31;

    for (int i = tid; i < CC; i += 256) sxc[i] = g_xc[(size_t)row * CC + i];
    if (tid < NCAND) scand[tid] = g_cand[(size_t)row * NCAND + tid];
    __syncthreads();

    const float4* xs4 = (const float4*)sxc;
    #pragma unroll
    for (int j = 0; j < NCAND / 8; j++) {
        int ci = wid * 8 + j;
        int d = scand[ci];
        const float4* wr = (const float4*)(ew + ((size_t)r * DD + d) * CC);
        float acc = 0.f;
        #pragma unroll
        for (int it = 0; it < 8; it++) {
            float4 a = xs4[it * 32 + lane];
            float4 b = wr[it * 32 + lane];
            acc += a.x * b.x;
            acc += a.y * b.y;
            acc += a.z * b.z;
            acc += a.w * b.w;
        }
        #pragma unroll
        for (int o = 16; o > 0; o >>= 1)
            acc += __shfl_xor_sync(0xFFFFFFFFu, acc, o);
        if (lane == 0) sval[ci] = acc + eb[(size_t)r * DD + d];
    }
    __syncthreads();

    // exact top-32 of 64: rank by (value desc, index asc)
    if (tid < NCAND) {
        float v = sval[tid];
        int   d = scand[tid];
        int rank = 0;
        #pragma unroll
        for (int j = 0; j < NCAND; j++) {
            float vj = sval[j];
            int   dj = scand[j];
            rank += (vj > v) || (vj == v && dj < d);
        }
        if (rank < KK) {
            g_idx [(size_t)row * KK + rank] = d;
            g_vals[(size_t)row * KK + rank] = v > 0.f ? v : 0.f;   // relu
        }
    }
}

// ---------------- sparse decode: out = sum_j val_j * dwT[r][idx_j][:] + db ----
__global__ __launch_bounds__(256)
void decode_kernel(const float* __restrict__ db, float* __restrict__ out) {
    __shared__ float sval[KK];
    __shared__ int   sidx[KK];
    const int b = blockIdx.x;
    const int r = blockIdx.y;
    const int tid = threadIdx.x;
    const size_t row = (size_t)b * RR + r;
    if (tid < KK) {
        sval[tid] = g_vals[row * KK + tid];
        sidx[tid] = g_idx [row * KK + tid];
    }
    __syncthreads();
    const float* dwr = g_dwT + (size_t)r * DD * CC;
    #pragma unroll
    for (int it = 0; it < 4; it++) {
        int c = tid + it * 256;
        float acc = db[r * CC + c];
        #pragma unroll
        for (int j = 0; j < KK; j++)
            acc += sval[j] * dwr[(size_t)sidx[j] * CC + c];
        out[row * CC + c] = acc;
    }
}

// ---------------- launch ------------------------------------------------------
extern "C" void kernel_launch(void* const* d_in, const int* in_sizes, int n_in,
                              void* d_out, int out_size) {
    const float* x  = (const float*)d_in[0];   // [B,R,C]
    const float* ew = (const float*)d_in[1];   // [R,D,C]
    const float* eb = (const float*)d_in[2];   // [R,D]
    const float* dw = (const float*)d_in[3];   // [R,C,D]
    const float* db = (const float*)d_in[4];   // [R,C]
    float* out = (float*)d_out;                // [B,R,C]

    __nv_bfloat16* h_ptr;  cudaGetSymbolAddress((void**)&h_ptr, g_h);
    __nv_bfloat16* a_ptr;  cudaGetSymbolAddress((void**)&a_ptr, g_Ah);
    __nv_bfloat16* b_ptr;  cudaGetSymbolAddress((void**)&b_ptr, g_Bh);

    prep_x_kernel<<<(BB * RR * CC) / 256, 256>>>(x, db);
    prep_w_kernel<<<(RR * DD * CC) / 256, 256>>>(ew);
    transpose_dw_kernel<<<dim3(DD / 32, CC / 32, RR), dim3(32, 8)>>>(dw);
    encoder_gemm_kernel<<<dim3(BB / 128, DD / 128, RR), 128>>>(a_ptr, b_ptr, eb, h_ptr);
    topk_kernel<<<BB * RR, 256>>>(h_ptr);
    refine_kernel<<<BB * RR, 256>>>(ew, eb);
    decode_kernel<<<dim3(BB, RR), 256>>>(db, out);
}

// round 6
// speedup vs baseline: 1.4800x; 1.4800x over previous
#include <cuda_runtime.h>
#include <cuda_bf16.h>
#include <cstdint>

// Problem constants
#define BB 1024
#define RR 8
#define CC 1024
#define DD 16384
#define KK 32
#define NCAND 64
#define SST 40          // smem row stride in bf16 (80B: 16B aligned, LDSM conflict-free)
#define NSTG 3          // cp.async pipeline depth
#define STG_ELEMS (128 * SST)          // bf16 elems per operand-stage
#define GEMM_SMEM (NSTG * 2 * STG_ELEMS * 2)   // 61440 bytes

// ---------------- device scratch (allocation-free rule: __device__ globals) ----
__device__ __nv_bfloat16 g_h  [(size_t)BB * RR * DD];        // 256 MB approx h (bf16)
__device__ float         g_xc [(size_t)BB * RR * CC];        // 32 MB  x - decoder_b (fp32)
__device__ __nv_bfloat16 g_Ah [(size_t)RR * BB * CC];        // 16 MB  bf16 acts [r][b][c]
__device__ __nv_bfloat16 g_Bh [(size_t)RR * DD * CC];        // 256 MB bf16 weights [r][d][c]
__device__ float         g_dwT[(size_t)RR * DD * CC];        // 512 MB decoder_w transposed
__device__ int           g_cand[(size_t)BB * RR * NCAND];
__device__ float         g_vals[(size_t)BB * RR * KK];
__device__ int           g_idx [(size_t)BB * RR * KK];

// ---------------- prep ----------------------------------------------------------
__global__ void prep_x_kernel(const float* __restrict__ x,
                              const float* __restrict__ db) {
    int idx = blockIdx.x * blockDim.x + threadIdx.x;
    int b = idx >> 13;
    int r = (idx >> 10) & 7;
    int c = idx & 1023;
    float xc = x[idx] - db[r * CC + c];
    g_xc[idx] = xc;
    g_Ah[((size_t)r * BB + b) * CC + c] = __float2bfloat16(xc);
}

__global__ void prep_w_kernel(const float* __restrict__ ew) {
    int idx = blockIdx.x * blockDim.x + threadIdx.x;
    g_Bh[idx] = __float2bfloat16(ew[idx]);
}

__global__ void transpose_dw_kernel(const float* __restrict__ dw) {
    __shared__ float tile[32][33];
    int d0 = blockIdx.x * 32;
    int c0 = blockIdx.y * 32;
    int r  = blockIdx.z;
    int tx = threadIdx.x, ty = threadIdx.y;
    #pragma unroll
    for (int j = 0; j < 4; j++) {
        int c = c0 + ty + j * 8;
        tile[ty + j * 8][tx] = dw[((size_t)r * CC + c) * DD + d0 + tx];
    }
    __syncthreads();
    #pragma unroll
    for (int j = 0; j < 4; j++) {
        int d = d0 + ty + j * 8;
        g_dwT[((size_t)r * DD + d) * CC + c0 + tx] = tile[tx][ty + j * 8];
    }
}

// ---------------- encoder GEMM: bf16 mma m16n8k16, 3-stage cp.async + ldmatrix --
// Block 128x128, 8 warps (2x4), warp tile 64x32.

__device__ __forceinline__ void mma16816(float* c, const uint32_t* a,
                                         uint32_t b0, uint32_t b1) {
    asm volatile(
        "mma.sync.aligned.m16n8k16.row.col.f32.bf16.bf16.f32 "
        "{%0,%1,%2,%3}, {%4,%5,%6,%7}, {%8,%9}, {%0,%1,%2,%3};\n"
        : "+f"(c[0]), "+f"(c[1]), "+f"(c[2]), "+f"(c[3])
        : "r"(a[0]), "r"(a[1]), "r"(a[2]), "r"(a[3]), "r"(b0), "r"(b1));
}

__device__ __forceinline__ void ldsm4(uint32_t* d, uint32_t addr) {
    asm volatile("ldmatrix.sync.aligned.m8n8.x4.shared.b16 {%0,%1,%2,%3}, [%4];"
                 : "=r"(d[0]), "=r"(d[1]), "=r"(d[2]), "=r"(d[3]) : "r"(addr));
}

__device__ __forceinline__ void cp16(uint32_t dst, const void* src) {
    asm volatile("cp.async.cg.shared.global [%0], [%1], 16;\n"
                 :: "r"(dst), "l"(src) : "memory");
}

__global__ __launch_bounds__(256, 2)
void encoder_gemm_kernel(const __nv_bfloat16* __restrict__ Ap,
                         const __nv_bfloat16* __restrict__ Bp,
                         const float* __restrict__ eb,
                         __nv_bfloat16* __restrict__ H) {
    extern __shared__ __nv_bfloat16 smem[];   // [NSTG][A|B][128*SST]
    const int mt = blockIdx.x;        // 8  (fastest: B-tile L2 reuse)
    const int nt = blockIdx.y;        // 128
    const int r  = blockIdx.z;        // 8
    const int tid = threadIdx.x;
    const int wid = tid >> 5, lane = tid & 31;
    const int wm = wid >> 2, wn = wid & 3;    // 2x4 warps, 64x32 per warp
    const int g = lane >> 2, t = lane & 3;

    float acc[4][4][4];
    #pragma unroll
    for (int i = 0; i < 4; i++)
        #pragma unroll
        for (int j = 0; j < 4; j++)
            #pragma unroll
            for (int q = 0; q < 4; q++) acc[i][j][q] = 0.f;

    const uint32_t s0 = (uint32_t)__cvta_generic_to_shared(smem);

    // global->smem: per operand 512 16B-segments per stage; 2 per thread
    const int row0 = tid >> 2, seg0 = (tid & 3) * 8;            // j=0
    const int row1 = (tid + 256) >> 2, seg1 = ((tid + 256) & 3) * 8;
    const size_t aG0 = ((size_t)r * BB + (size_t)mt * 128 + row0) * CC + seg0;
    const size_t aG1 = ((size_t)r * BB + (size_t)mt * 128 + row1) * CC + seg1;
    const size_t bG0 = ((size_t)r * DD + (size_t)nt * 128 + row0) * CC + seg0;
    const size_t bG1 = ((size_t)r * DD + (size_t)nt * 128 + row1) * CC + seg1;
    const uint32_t d0b = (uint32_t)(row0 * SST + seg0) * 2;
    const uint32_t d1b = (uint32_t)(row1 * SST + seg1) * 2;

    auto prefetch = [&](int kt) {
        int stg = kt % NSTG;
        uint32_t aBase = s0 + stg * (2 * STG_ELEMS * 2);
        uint32_t bBase = aBase + STG_ELEMS * 2;
        size_t ko = (size_t)kt * 32;
        cp16(aBase + d0b, Ap + aG0 + ko);
        cp16(aBase + d1b, Ap + aG1 + ko);
        cp16(bBase + d0b, Bp + bG0 + ko);
        cp16(bBase + d1b, Bp + bG1 + ko);
    };

    // ldmatrix per-lane base offsets (bytes within operand-stage)
    const uint32_t fRow = lane & 15;
    const uint32_t fK   = (lane >> 4) * 8;
    const uint32_t aF = ((wm * 64 + fRow) * SST + fK) * 2;
    const uint32_t bF = ((wn * 32 + fRow) * SST + fK) * 2;

    prefetch(0);
    asm volatile("cp.async.commit_group;" ::: "memory");
    prefetch(1);
    asm volatile("cp.async.commit_group;" ::: "memory");

    const int NKT = CC / 32;   // 32
    for (int kt = 0; kt < NKT; kt++) {
        asm volatile("cp.async.wait_group 1;" ::: "memory");   // group kt done
        __syncthreads();
        if (kt + 2 < NKT) prefetch(kt + 2);
        asm volatile("cp.async.commit_group;" ::: "memory");

        int stg = kt % NSTG;
        const uint32_t baseA = s0 + stg * (2 * STG_ELEMS * 2) + aF;
        const uint32_t baseB = s0 + stg * (2 * STG_ELEMS * 2) + STG_ELEMS * 2 + bF;
        #pragma unroll
        for (int ks = 0; ks < 2; ks++) {
            const int ko = ks * 16;
            uint32_t afr[4][4], bq[2][4];
            #pragma unroll
            for (int mi = 0; mi < 4; mi++) ldsm4(afr[mi], baseA + (mi * 16 * SST + ko) * 2);
            #pragma unroll
            for (int nb = 0; nb < 2; nb++) ldsm4(bq[nb], baseB + (nb * 16 * SST + ko) * 2);
            #pragma unroll
            for (int mi = 0; mi < 4; mi++)
                #pragma unroll
                for (int nb = 0; nb < 2; nb++) {
                    mma16816(acc[mi][2 * nb],     afr[mi], bq[nb][0], bq[nb][2]);
                    mma16816(acc[mi][2 * nb + 1], afr[mi], bq[nb][1], bq[nb][3]);
                }
        }
        __syncthreads();    // compute done before stage reuse by prefetch(kt+3)
    }

    // epilogue: h = acc + encoder_b -> bf16
    const size_t ebBase = (size_t)r * DD;
    #pragma unroll
    for (int mi = 0; mi < 4; mi++) {
        int b0 = mt * 128 + wm * 64 + mi * 16 + g;
        #pragma unroll
        for (int ni = 0; ni < 4; ni++) {
            int dd0 = nt * 128 + wn * 32 + ni * 8 + 2 * t;
            float e0 = eb[ebBase + dd0];
            float e1 = eb[ebBase + dd0 + 1];
            __nv_bfloat162 v0, v1;
            v0.x = __float2bfloat16(acc[mi][ni][0] + e0);
            v0.y = __float2bfloat16(acc[mi][ni][1] + e1);
            v1.x = __float2bfloat16(acc[mi][ni][2] + e0);
            v1.y = __float2bfloat16(acc[mi][ni][3] + e1);
            *(__nv_bfloat162*)&H[((size_t)b0 * RR + r) * DD + dd0]       = v0;
            *(__nv_bfloat162*)&H[((size_t)(b0 + 8) * RR + r) * DD + dd0] = v1;
        }
    }
}

// ---------------- approx top-64 candidates: 2-pass radix on 16-bit bf16 keys ----
__global__ __launch_bounds__(256)
void topk_kernel(const __nv_bfloat16* __restrict__ H) {
    __shared__ uint16_t skey[DD];             // 32 KB
    __shared__ int hist[256];
    __shared__ int s_sel, s_remaining, s_cnt, s_tiecnt;
    __shared__ int out_idx[NCAND];
    __shared__ int tie_idx[192];

    const int row = blockIdx.x;
    const int tid = threadIdx.x;
    const uint4* h4 = (const uint4*)(H + (size_t)row * DD);

    for (int c = tid; c < DD / 8; c += 256) {
        uint4 v = h4[c];
        uint32_t ws[4] = {v.x, v.y, v.z, v.w};
        #pragma unroll
        for (int q = 0; q < 4; q++) {
            uint16_t lo = (uint16_t)(ws[q] & 0xFFFF);
            uint16_t hi = (uint16_t)(ws[q] >> 16);
            skey[c * 8 + 2 * q]     = (lo & 0x8000) ? (uint16_t)~lo : (uint16_t)(lo | 0x8000);
            skey[c * 8 + 2 * q + 1] = (hi & 0x8000) ? (uint16_t)~hi : (uint16_t)(hi | 0x8000);
        }
    }
    hist[tid] = 0;
    __syncthreads();

    for (int i = tid; i < DD; i += 256) atomicAdd(&hist[skey[i] >> 8], 1);
    __syncthreads();
    if (tid == 0) {
        int cum = 0, v = 255;
        for (; v > 0; v--) {
            if (cum + hist[v] >= NCAND) break;
            cum += hist[v];
        }
        s_sel = v;
        s_remaining = NCAND - cum;
    }
    __syncthreads();
    const int hb = s_sel;
    const int rem = s_remaining;
    __syncthreads();
    hist[tid] = 0;
    __syncthreads();

    for (int i = tid; i < DD; i += 256) {
        uint16_t k = skey[i];
        if ((k >> 8) == hb) atomicAdd(&hist[k & 0xFF], 1);
    }
    __syncthreads();
    if (tid == 0) {
        int cum = 0, v = 255;
        for (; v > 0; v--) {
            if (cum + hist[v] >= rem) break;
            cum += hist[v];
        }
        s_sel = (hb << 8) | v;
        s_cnt = 0;
        s_tiecnt = 0;
    }
    __syncthreads();
    const uint16_t T = (uint16_t)s_sel;

    for (int i = tid; i < DD; i += 256) {
        uint16_t k = skey[i];
        if (k > T) {
            int p = atomicAdd(&s_cnt, 1);
            out_idx[p] = i;
        } else if (k == T) {
            int p = atomicAdd(&s_tiecnt, 1);
            if (p < 192) tie_idx[p] = i;
        }
    }
    __syncthreads();
    if (tid == 0) {
        int gcnt = s_cnt;
        int need = NCAND - gcnt;
        if (s_tiecnt <= 192) {
            for (int a = 0; a < need; a++) out_idx[gcnt + a] = tie_idx[a];
        } else {
            int taken = 0;
            for (int i = 0; i < DD && taken < need; i++)
                if (skey[i] == T) out_idx[gcnt + taken++] = i;
        }
    }
    __syncthreads();
    if (tid < NCAND) g_cand[(size_t)row * NCAND + tid] = out_idx[tid];
}

// ---------------- exact fp32 refine of 64 candidates -> top-32 ------------------
__global__ __launch_bounds__(256)
void refine_kernel(const float* __restrict__ ew, const float* __restrict__ eb) {
    __shared__ float sxc[CC];
    __shared__ float sval[NCAND];
    __shared__ int   scand[NCAND];

    const int row = blockIdx.x;
    const int r   = row & 7;
    const int tid = threadIdx.x;
    const int wid = tid >> 5, lane = tid & 31;

    for (int i = tid; i < CC; i += 256) sxc[i] = g_xc[(size_t)row * CC + i];
    if (tid < NCAND) scand[tid] = g_cand[(size_t)row * NCAND + tid];
    __syncthreads();

    const float4* xs4 = (const float4*)sxc;
    #pragma unroll
    for (int j = 0; j < NCAND / 8; j++) {
        int ci = wid * 8 + j;
        int d = scand[ci];
        const float4* wr = (const float4*)(ew + ((size_t)r * DD + d) * CC);
        float acc = 0.f;
        #pragma unroll
        for (int it = 0; it < 8; it++) {
            float4 a = xs4[it * 32 + lane];
            float4 b = wr[it * 32 + lane];
            acc += a.x * b.x;
            acc += a.y * b.y;
            acc += a.z * b.z;
            acc += a.w * b.w;
        }
        #pragma unroll
        for (int o = 16; o > 0; o >>= 1)
            acc += __shfl_xor_sync(0xFFFFFFFFu, acc, o);
        if (lane == 0) sval[ci] = acc + eb[(size_t)r * DD + d];
    }
    __syncthreads();

    if (tid < NCAND) {
        float v = sval[tid];
        int   d = scand[tid];
        int rank = 0;
        #pragma unroll
        for (int j = 0; j < NCAND; j++) {
            float vj = sval[j];
            int   dj = scand[j];
            rank += (vj > v) || (vj == v && dj < d);
        }
        if (rank < KK) {
            g_idx [(size_t)row * KK + rank] = d;
            g_vals[(size_t)row * KK + rank] = v > 0.f ? v : 0.f;
        }
    }
}

// ---------------- sparse decode --------------------------------------------------
__global__ __launch_bounds__(256)
void decode_kernel(const float* __restrict__ db, float* __restrict__ out) {
    __shared__ float sval[KK];
    __shared__ int   sidx[KK];
    const int b = blockIdx.x;
    const int r = blockIdx.y;
    const int tid = threadIdx.x;
    const size_t row = (size_t)b * RR + r;
    if (tid < KK) {
        sval[tid] = g_vals[row * KK + tid];
        sidx[tid] = g_idx [row * KK + tid];
    }
    __syncthreads();
    const float* dwr = g_dwT + (size_t)r * DD * CC;
    #pragma unroll
    for (int it = 0; it < 4; it++) {
        int c = tid + it * 256;
        float acc = db[r * CC + c];
        #pragma unroll
        for (int j = 0; j < KK; j++)
            acc += sval[j] * dwr[(size_t)sidx[j] * CC + c];
        out[row * CC + c] = acc;
    }
}

// ---------------- launch ----------------------------------------------------------
extern "C" void kernel_launch(void* const* d_in, const int* in_sizes, int n_in,
                              void* d_out, int out_size) {
    const float* x  = (const float*)d_in[0];
    const float* ew = (const float*)d_in[1];
    const float* eb = (const float*)d_in[2];
    const float* dw = (const float*)d_in[3];
    const float* db = (const float*)d_in[4];
    float* out = (float*)d_out;

    __nv_bfloat16* h_ptr;  cudaGetSymbolAddress((void**)&h_ptr, g_h);
    __nv_bfloat16* a_ptr;  cudaGetSymbolAddress((void**)&a_ptr, g_Ah);
    __nv_bfloat16* b_ptr;  cudaGetSymbolAddress((void**)&b_ptr, g_Bh);

    cudaFuncSetAttribute(encoder_gemm_kernel,
                         cudaFuncAttributeMaxDynamicSharedMemorySize, GEMM_SMEM);

    prep_x_kernel<<<(BB * RR * CC) / 256, 256>>>(x, db);
    prep_w_kernel<<<(RR * DD * CC) / 256, 256>>>(ew);
    transpose_dw_kernel<<<dim3(DD / 32, CC / 32, RR), dim3(32, 8)>>>(dw);
    encoder_gemm_kernel<<<dim3(BB / 128, DD / 128, RR), 256, GEMM_SMEM>>>(a_ptr, b_ptr, eb, h_ptr);
    topk_kernel<<<BB * RR, 256>>>(h_ptr);
    refine_kernel<<<BB * RR, 256>>>(ew, eb);
    decode_kernel<<<dim3(BB, RR), 256>>>(db, out);
}